// round 2
// baseline (speedup 1.0000x reference)
#include <cuda_runtime.h>
#include <math.h>

#define NF   24
#define FS   8
#define DY   32
#define DX   32
#define SEQL 300
#define TOTAL (NF*FS*DY*DX*SEQL)   // 58,982,400 floats
#define N4    (TOTAL/4)            // 14,745,600 float4
#define ROW4  (SEQL/4)             // 75

#define A_THREADS 256
#define A_ILP     4
#define A_BLOCKS  (N4 / (A_THREADS * A_ILP))   // 14400 exactly

__device__ float g_max;   // global max of input; reset to 0.0f via memset each replay

__constant__ double c_lefts[NF] = {
    0.05, 0.0717, 0.0935, 0.1152, 0.137, 0.1587, 0.1804, 0.2022,
    0.2239, 0.2457, 0.2674, 0.2891, 0.3109, 0.3326, 0.3543, 0.3761,
    0.3978, 0.4196, 0.4413, 0.463, 0.4848, 0.5065, 0.5283, 0.55
};

// selected token: s==2 || s==3 || 9<=s<=108
__device__ __forceinline__ bool sel_tok(int s) {
    return ((unsigned)(s - 9) < 100u) || ((s & ~1) == 2);
}

// Pass A: out = in * (sel ? 0.918 : 1.0) everywhere + grid max of input.
// 4 independent LDG.128 issued up front per thread (MLP 4), exact-size grid.
__global__ void __launch_bounds__(A_THREADS)
apply_weaken_max(const float4* __restrict__ in, float4* __restrict__ out) {
    const int t      = blockIdx.x * A_THREADS + threadIdx.x;
    const int stride = A_BLOCKS * A_THREADS;   // 3,686,400

    int    idx[A_ILP];
    float4 v[A_ILP];
    #pragma unroll
    for (int k = 0; k < A_ILP; k++) { idx[k] = t + k * stride; }
    #pragma unroll
    for (int k = 0; k < A_ILP; k++) { v[k] = in[idx[k]]; }

    float mx = 0.f;
    #pragma unroll
    for (int k = 0; k < A_ILP; k++) {
        float4 x = v[k];
        mx = fmaxf(mx, fmaxf(fmaxf(x.x, x.y), fmaxf(x.z, x.w)));
        int s0 = (idx[k] % ROW4) * 4;
        float4 o;
        o.x = sel_tok(s0    ) ? x.x * 0.918f : x.x;
        o.y = sel_tok(s0 + 1) ? x.y * 0.918f : x.y;
        o.z = sel_tok(s0 + 2) ? x.z * 0.918f : x.z;
        o.w = sel_tok(s0 + 3) ? x.w * 0.918f : x.w;
        out[idx[k]] = o;
    }

    // block max -> one atomic per block
    #pragma unroll
    for (int off = 16; off; off >>= 1)
        mx = fmaxf(mx, __shfl_xor_sync(0xffffffffu, mx, off));
    __shared__ float sm[A_THREADS / 32];
    if ((threadIdx.x & 31) == 0) sm[threadIdx.x >> 5] = mx;
    __syncthreads();
    if (threadIdx.x < (A_THREADS / 32)) {
        mx = sm[threadIdx.x];
        #pragma unroll
        for (int off = (A_THREADS / 64); off; off >>= 1)
            mx = fmaxf(mx, __shfl_xor_sync(0xffffffffu, mx, off));
        if (threadIdx.x == 0)
            atomicMax((int*)&g_max, __float_as_int(mx));   // all inputs >= 0
    }
}

// Pass B: one block per (frame, fs). Prologue computes the frame's bbox +
// normalized gaussian patch in shared; body overwrites bbox x selected tokens:
//   out = in + 0.125 * patch * g_max   (weaken factor is 1.0 inside bbox)
__global__ void __launch_bounds__(256)
apply_strengthen(const float* __restrict__ in, float* __restrict__ out) {
    const int f  = blockIdx.x >> 3;     // /FS
    const int fs = blockIdx.x & 7;
    const int tid = threadIdx.x;

    __shared__ float s_patch[160];      // 16 rows x 10 cols (zero-padded to w)
    __shared__ int   s_left, s_w;
    __shared__ float s_norm;

    // bbox (Python int()/round() semantics, in double)
    double l = c_lefts[f];
    double r = rint((l + 0.3) * 10000.0) / 10000.0;
    int left  = (int)((double)DX * l);
    int right = (int)((double)DX * r);
    int w = right - left;               // 9 or 10
    const int h = 16;                   // bottom(24) - top(8)
    if (tid == 0) { s_left = left; s_w = w; }

    if (tid < 160) {
        int i = tid / 10, j = tid % 10;
        float v = 0.f;
        if (j < w) {
            float x  = (float)i * ((float)h / (float)(h - 1));
            float y  = (float)j * ((float)w / (float)(w - 1));
            float sx = (float)h / 3.0f;
            float sy = (float)w / 3.0f;
            float dx = x - (float)(h / 2);
            float dy = y - (float)(w / 2);
            v = expf(-(dx * dx / (2.f * sx * sx) + dy * dy / (2.f * sy * sy)));
        }
        s_patch[tid] = v;
    }
    __syncthreads();
    if (tid == 0) {
        float m = 0.f;
        #pragma unroll 8
        for (int k = 0; k < 160; k++) m = fmaxf(m, s_patch[k]);
        s_norm = m;
    }
    __syncthreads();
    const float inv_norm_scale = g_max / s_norm;   // patch/norm * max (INJECTION_SCALE=1)
    const int wloc = s_w, lloc = s_left;

    // 160 positions x 102 tokens
    const int row0 = (f * FS + fs) * DY;   // frame-slice base row (y index offset)
    for (int e = tid; e < 160 * 102; e += 256) {
        int p  = e / 102;
        int tk = e - p * 102;
        int yrow = p / 10;
        int xoff = p - yrow * 10;
        if (xoff >= wloc) continue;
        int tok = (tk < 2) ? (tk + 2) : (tk + 7);   // {2,3}, 9..108
        float wm = s_patch[p] * inv_norm_scale;     // > 0 inside bbox
        int addr = (((row0 + 8 + yrow) * DX) + (lloc + xoff)) * SEQL + tok;
        out[addr] = in[addr] + 0.125f * wm;
    }
}

extern "C" void kernel_launch(void* const* d_in, const int* in_sizes, int n_in,
                              void* d_out, int out_size) {
    const float* in = (const float*)d_in[0];
    float* out = (float*)d_out;

    static void* gmax_addr = nullptr;
    if (!gmax_addr) cudaGetSymbolAddress(&gmax_addr, g_max);

    cudaMemsetAsync(gmax_addr, 0, sizeof(float));   // g_max = 0.0f (inputs >= 0)
    apply_weaken_max<<<A_BLOCKS, A_THREADS>>>((const float4*)in, (float4*)out);
    apply_strengthen<<<NF * FS, 256>>>(in, out);
}